// round 14
// baseline (speedup 1.0000x reference)
#include <cuda_runtime.h>
#include <cstdint>

namespace {
constexpr int Bq = 8, Tq = 2048, Eq = 2048;
constexpr int TS = 128;          // s tile (M)
constexpr int TE = 64;           // e tile (N)
constexpr int KT = 32;           // t chunk (4 x k8)
constexpr int PAD = 8;           // smem B row pad (words) -> conflict-free frags
constexpr int BROW = TE + PAD;   // 72 words per t-row
constexpr int WS_ELEMS = TS + Tq;
constexpr int NS = 4;            // cp.async ring stages (prefetch depth 3)
constexpr int STAGE_W = KT * BROW;                        // 2304 words
constexpr int SMEM_BYTES = (WS_ELEMS + NS * STAGE_W) * 4; // 45568 B

// x is fed to HMMA as raw fp32 (hardware truncates to tf32, RZ). Mean relative
// shrink of |x| is 2^-11 * ln2 ~= 3.38e-4; fold the compensation into w.
constexpr float XCOMP = 1.000338f;

__device__ __forceinline__ float tf32r(float x) {   // round-to-nearest tf32
    float y; asm("cvt.rna.tf32.f32 %0, %1;" : "=f"(y) : "f"(x)); return y;
}
__device__ __forceinline__ uint32_t smem_u32(const void* p) {
    return (uint32_t)__cvta_generic_to_shared(p);
}
__device__ __forceinline__ void cp16(uint32_t dst, const void* src) {
    asm volatile("cp.async.cg.shared.global [%0], [%1], 16;"
                 :: "r"(dst), "l"(src));
}
__device__ __forceinline__ void cp_commit() {
    asm volatile("cp.async.commit_group;");
}
template <int N> __device__ __forceinline__ void cp_wait() {
    asm volatile("cp.async.wait_group %0;" :: "n"(N));
}
// Legacy tensor-core path: available on plain compute_103 (sm_80 baseline).
__device__ __forceinline__ void mma1688(float* d, float a0, float a1, float a2,
                                        float a3, float b0, float b1) {
    asm volatile(
        "mma.sync.aligned.m16n8k8.row.col.f32.tf32.tf32.f32 "
        "{%0,%1,%2,%3}, {%4,%5,%6,%7}, {%8,%9}, {%0,%1,%2,%3};"
        : "+f"(d[0]), "+f"(d[1]), "+f"(d[2]), "+f"(d[3])
        : "r"(__float_as_uint(a0)), "r"(__float_as_uint(a1)),
          "r"(__float_as_uint(a2)), "r"(__float_as_uint(a3)),
          "r"(__float_as_uint(b0)), "r"(__float_as_uint(b1)));
}
}  // namespace

// out[b,s,e] = bias[s] + sum_{t<=s} x[b,t,e]*weight[s-t]
// GEMM D[s,e] = A[s,t]*B[t,e]; A = lower-tri Toeplitz from a 22-reg sliding
// window over the smem weight table; B = x staged by cp.async (raw fp32, HW
// tf32-truncation compensated in w). 4-stage ring, one barrier per chunk,
// warp-uniform skip of all-zero diagonal MMA tiles, bounded ws prologue.
// 128 thr = 4 warps (2m x 2n), warp tile 64x32; HW scheduler, 4096 blocks.
__global__ __launch_bounds__(128, 4)
void toeplitz_mma_kernel(const float* __restrict__ x, const float* __restrict__ w,
                         const float* __restrict__ bias, float* __restrict__ out) {
    extern __shared__ float sm[];
    float* ws = sm;                          // ws[TS+d] = tf32(w[d]*XCOMP); front 0
    float* bs = sm + WS_ELEMS;               // NS stages of KT x BROW (t-major)

    const int tid = threadIdx.x, wid = tid >> 5, lane = tid & 31;
    const int grp = lane >> 2, tid4 = lane & 3;     // mma quad coords
    const int wm = wid >> 1, wn = wid & 1;          // warp grid 2(m) x 2(n)
    const int e0 = blockIdx.x * TE;
    const int s0 = ((int)gridDim.y - 1 - (int)blockIdx.y) * TS;  // heavy first
    const int b  = blockIdx.z;

    // Bounded prologue: this CTA only reads ws[0 .. s0+255].
    const int ws_need = min(WS_ELEMS, s0 + 2 * TS);
    for (int i = tid; i < ws_need; i += 128)
        ws[i] = (i < TS) ? 0.0f : tf32r(w[i - TS] * XCOMP);
    __syncthreads();   // ws visible before first consume (cp.async overlaps)

    float acc[4][4][4];                      // [mt][nt][frag]
#pragma unroll
    for (int mt = 0; mt < 4; mt++)
#pragma unroll
        for (int nt = 0; nt < 4; nt++)
#pragma unroll
            for (int f = 0; f < 4; f++) acc[mt][nt][f] = 0.0f;

    const int nchunk = (s0 + TS) / KT;       // triangular cutoff (>= 4)
    const size_t xbase = ((size_t)b * Tq) * Eq + e0;
    const int wj0 = TS + s0 + wm * 64 + grp - tid4 - 28;  // A-window anchor
    const int bbase = wn * 32 + grp;
    const int smax = s0 + wm * 64 + 63;      // warp's max s row
    const int srow = tid >> 4;               // stage row base (0..7)
    const int scol = (tid & 15) * 4;         // stage word col (16B granule)

    // Stage copy: 32 rows x 64 cols; thread owns rows srow+8j, one 16B each.
    auto issue = [&](int k) {
        const int t0 = k * KT;
        float* stg = bs + (k & (NS - 1)) * STAGE_W;
#pragma unroll
        for (int j = 0; j < 4; j++) {
            const int r = srow + 8 * j;
            cp16(smem_u32(&stg[r * BROW + scol]),
                 &x[xbase + (size_t)(t0 + r) * Eq + scol]);
        }
        cp_commit();
    };

    issue(0);
    issue(1);
    issue(2);

    for (int k = 0; k < nchunk; k++) {
        // Chunk k must have landed; newer groups may stay pending.
        const int ahead = nchunk - 1 - k;    // groups issued beyond k (cap 2)
        if (ahead >= 2)      cp_wait<2>();
        else if (ahead == 1) cp_wait<1>();
        else                 cp_wait<0>();
        __syncthreads();   // publishes chunk k; proves consume(k-1) finished
        if (k + 3 < nchunk) issue(k + 3);    // overwrites chunk k-1's stage: safe

        const int t0 = k * KT;
        if (smax < t0) continue;             // whole warp tile is zero (diag)

        const float* stg = bs + (k & (NS - 1)) * STAGE_W;

        // Toeplitz A window: W[j] = ws[wj0 - t0 + 4j], j=0..21.
        // afr(mt,kk,f) = W[7 + 4*mt - 2*kk + {0,2,-1,1}] — static after unroll.
        float W[22];
        {
            const float* wp = &ws[wj0 - t0];
#pragma unroll
            for (int j = 0; j < 22; j++) W[j] = wp[4 * j];
        }

#pragma unroll
        for (int kk = 0; kk < 4; kk++) {
            if (smax < t0 + kk * 8) break;   // rest of chunk is zero
            float bfr[4][2];
            const float* bp = &stg[(kk * 8 + tid4) * BROW + bbase];
#pragma unroll
            for (int nt = 0; nt < 4; nt++) {
                bfr[nt][0] = bp[nt * 8];
                bfr[nt][1] = bp[nt * 8 + 4 * BROW];
            }
#pragma unroll
            for (int mt = 0; mt < 4; mt++) {
                // Zero-tile skip: max_s of this mt tile < min_t of kk slab.
                if (s0 + wm * 64 + mt * 16 + 15 < t0 + kk * 8) continue;
                const int j = 7 + 4 * mt - 2 * kk;
#pragma unroll
                for (int nt = 0; nt < 4; nt++)
                    mma1688(acc[mt][nt], W[j], W[j + 2], W[j - 1], W[j + 1],
                            bfr[nt][0], bfr[nt][1]);
            }
        }
    }

    // Epilogue: c0/c1 -> row grp, cols 2*tid4(+1); c2/c3 -> row grp+8.
#pragma unroll
    for (int mt = 0; mt < 4; mt++) {
        const int r0 = s0 + wm * 64 + mt * 16 + grp;
        const int r1 = r0 + 8;
        const float bv0 = bias[r0], bv1 = bias[r1];
        const int ec = e0 + wn * 32 + tid4 * 2;
#pragma unroll
        for (int nt = 0; nt < 4; nt++) {
            float2 v0 = make_float2(acc[mt][nt][0] + bv0, acc[mt][nt][1] + bv0);
            float2 v1 = make_float2(acc[mt][nt][2] + bv1, acc[mt][nt][3] + bv1);
            *(float2*)&out[((size_t)b * Tq + r0) * Eq + ec + nt * 8] = v0;
            *(float2*)&out[((size_t)b * Tq + r1) * Eq + ec + nt * 8] = v1;
        }
    }
}

extern "C" void kernel_launch(void* const* d_in, const int* in_sizes, int n_in,
                              void* d_out, int out_size) {
    const float* x      = (const float*)d_in[0];
    const float* weight = (const float*)d_in[1];
    const float* bias   = (const float*)d_in[2];
    float* out          = (float*)d_out;

    static bool attr_set = false;
    if (!attr_set) {
        cudaFuncSetAttribute(toeplitz_mma_kernel,
                             cudaFuncAttributeMaxDynamicSharedMemorySize,
                             SMEM_BYTES);
        attr_set = true;
    }
    dim3 grid(Eq / TE, Tq / TS, Bq);   // (32, 16, 8) = 4096 blocks
    toeplitz_mma_kernel<<<grid, 128, SMEM_BYTES>>>(x, weight, bias, out);
}

// round 17
// speedup vs baseline: 1.0528x; 1.0528x over previous
#include <cuda_runtime.h>
#include <cstdint>

namespace {
constexpr int Bq = 8, Tq = 2048, Eq = 2048;
constexpr int TS = 128;          // s tile (M)
constexpr int TE = 64;           // e tile (N)
constexpr int KT = 32;           // t chunk (4 x k8)
constexpr int BROWP = 40;        // pair slab row stride: 32 cols + 8 pad words
constexpr int WS_ELEMS = TS + Tq;
constexpr int NS = 4;            // cp.async ring stages (prefetch depth 3)
constexpr int STAGE_P = KT * BROWP;                       // 1280 words/pair-stage
constexpr int SMEM_BYTES = (WS_ELEMS + 2 * NS * STAGE_P) * 4;  // 49664 B

// x is fed to HMMA as raw fp32 (hardware truncates to tf32, RZ). Mean relative
// shrink of |x| is 2^-11 * ln2 ~= 3.38e-4; fold the compensation into w.
constexpr float XCOMP = 1.000338f;

__device__ __forceinline__ float tf32r(float x) {   // round-to-nearest tf32
    float y; asm("cvt.rna.tf32.f32 %0, %1;" : "=f"(y) : "f"(x)); return y;
}
__device__ __forceinline__ uint32_t smem_u32(const void* p) {
    return (uint32_t)__cvta_generic_to_shared(p);
}
__device__ __forceinline__ void cp16(uint32_t dst, const void* src) {
    asm volatile("cp.async.cg.shared.global [%0], [%1], 16;"
                 :: "r"(dst), "l"(src));
}
__device__ __forceinline__ void cp_commit() {
    asm volatile("cp.async.commit_group;");
}
template <int N> __device__ __forceinline__ void cp_wait() {
    asm volatile("cp.async.wait_group %0;" :: "n"(N));
}
__device__ __forceinline__ void bar_pair(int id) {   // 64-thread named barrier
    asm volatile("bar.sync %0, 64;" :: "r"(id) : "memory");
}
// Legacy tensor-core path: available on plain compute_103 (sm_80 baseline).
__device__ __forceinline__ void mma1688(float* d, float a0, float a1, float a2,
                                        float a3, float b0, float b1) {
    asm volatile(
        "mma.sync.aligned.m16n8k8.row.col.f32.tf32.tf32.f32 "
        "{%0,%1,%2,%3}, {%4,%5,%6,%7}, {%8,%9}, {%0,%1,%2,%3};"
        : "+f"(d[0]), "+f"(d[1]), "+f"(d[2]), "+f"(d[3])
        : "r"(__float_as_uint(a0)), "r"(__float_as_uint(a1)),
          "r"(__float_as_uint(a2)), "r"(__float_as_uint(a3)),
          "r"(__float_as_uint(b0)), "r"(__float_as_uint(b1)));
}
}  // namespace

// out[b,s,e] = bias[s] + sum_{t<=s} x[b,t,e]*weight[s-t]
// GEMM D[s,e] = A[s,t]*B[t,e]; A = lower-tri Toeplitz from a 22-reg sliding
// window over the smem weight table; B = x staged by cp.async (raw fp32, HW
// tf32-truncation compensated in w). 4-stage ring.
// Warp-PAIR decoupling: warps sharing wn (e-half) form a 64-thread domain
// with a PRIVATE B slab (32t x 32e, stride 40) and a named barrier — the two
// pairs never convoy each other, halving per-chunk pipeline bubbles.
// 128 thr = 4 warps (2m x 2n), warp tile 64x32; HW scheduler, 4096 blocks.
__global__ __launch_bounds__(128, 4)
void toeplitz_mma_kernel(const float* __restrict__ x, const float* __restrict__ w,
                         const float* __restrict__ bias, float* __restrict__ out) {
    extern __shared__ float sm[];
    float* ws = sm;                          // ws[TS+d] = tf32(w[d]*XCOMP); front 0
    float* bs = sm + WS_ELEMS;               // 2 pairs x NS stages of KT x BROWP

    const int tid = threadIdx.x, wid = tid >> 5, lane = tid & 31;
    const int grp = lane >> 2, tid4 = lane & 3;     // mma quad coords
    const int wm = wid >> 1, wn = wid & 1;          // warp grid 2(m) x 2(n)
    const int e0 = blockIdx.x * TE;
    const int s0 = ((int)gridDim.y - 1 - (int)blockIdx.y) * TS;  // heavy first
    const int b  = blockIdx.z;

    // Bounded prologue: this CTA only reads ws[0 .. s0+255].
    const int ws_need = min(WS_ELEMS, s0 + 2 * TS);
    for (int i = tid; i < ws_need; i += 128)
        ws[i] = (i < TS) ? 0.0f : tf32r(w[i - TS] * XCOMP);
    __syncthreads();   // ws visible to all warps before first consume

    float acc[4][4][4];                      // [mt][nt][frag]
#pragma unroll
    for (int mt = 0; mt < 4; mt++)
#pragma unroll
        for (int nt = 0; nt < 4; nt++)
#pragma unroll
            for (int f = 0; f < 4; f++) acc[mt][nt][f] = 0.0f;

    const int nchunk = (s0 + TS) / KT;       // triangular cutoff (>= 4)
    const size_t xbase = ((size_t)b * Tq) * Eq + e0;
    const int wj0 = TS + s0 + wm * 64 + grp - tid4 - 28;  // A-window anchor
    // Pair-local staging coords: 64 threads cover 32 rows x 8 16B-granules.
    const int ptid = wm * 32 + lane;         // 0..63 within pair
    const int pr0  = ptid >> 3;              // row base (0..7)
    const int pc   = (ptid & 7) * 4;         // word col within slab (0..28)
    float* pbs = bs + wn * NS * STAGE_P;     // this pair's ring
    const int ecol = wn * 32;                // pair's e offset within tile

    // Stage copy: pair-private 32 rows x 32 cols; 4 x 16B per thread.
    auto issue = [&](int k) {
        const int t0 = k * KT;
        float* stg = pbs + (k & (NS - 1)) * STAGE_P;
#pragma unroll
        for (int j = 0; j < 4; j++) {
            const int r = pr0 + 8 * j;
            cp16(smem_u32(&stg[r * BROWP + pc]),
                 &x[xbase + (size_t)(t0 + r) * Eq + ecol + pc]);
        }
        cp_commit();
    };

    issue(0);
    issue(1);
    issue(2);

    for (int k = 0; k < nchunk; k++) {
        // Chunk k must have landed; newer groups may stay pending.
        const int ahead = nchunk - 1 - k;    // groups issued beyond k (cap 2)
        if (ahead >= 2)      cp_wait<2>();
        else if (ahead == 1) cp_wait<1>();
        else                 cp_wait<0>();
        bar_pair(1 + wn);  // publishes chunk k within the pair; proves k-1 read
        if (k + 3 < nchunk) issue(k + 3);    // overwrites chunk k-1's stage: safe

        const float* stg = pbs + (k & (NS - 1)) * STAGE_P;

        // Toeplitz A window: W[j] = ws[wj0 - t0 + 4j], j=0..21.
        // afr(mt,kk,f) = W[7 + 4*mt - 2*kk + {0,2,-1,1}] — static after unroll.
        float W[22];
        {
            const float* wp = &ws[wj0 - k * KT];
#pragma unroll
            for (int j = 0; j < 22; j++) W[j] = wp[4 * j];
        }

#pragma unroll
        for (int kk = 0; kk < 4; kk++) {
            float bfr[4][2];
            const float* bp = &stg[(kk * 8 + tid4) * BROWP + grp];
#pragma unroll
            for (int nt = 0; nt < 4; nt++) {
                bfr[nt][0] = bp[nt * 8];
                bfr[nt][1] = bp[nt * 8 + 4 * BROWP];
            }
#pragma unroll
            for (int mt = 0; mt < 4; mt++) {
                const int j = 7 + 4 * mt - 2 * kk;
#pragma unroll
                for (int nt = 0; nt < 4; nt++)
                    mma1688(acc[mt][nt], W[j], W[j + 2], W[j - 1], W[j + 1],
                            bfr[nt][0], bfr[nt][1]);
            }
        }
    }

    // Epilogue: c0/c1 -> row grp, cols 2*tid4(+1); c2/c3 -> row grp+8.
#pragma unroll
    for (int mt = 0; mt < 4; mt++) {
        const int r0 = s0 + wm * 64 + mt * 16 + grp;
        const int r1 = r0 + 8;
        const float bv0 = bias[r0], bv1 = bias[r1];
        const int ec = e0 + wn * 32 + tid4 * 2;
#pragma unroll
        for (int nt = 0; nt < 4; nt++) {
            float2 v0 = make_float2(acc[mt][nt][0] + bv0, acc[mt][nt][1] + bv0);
            float2 v1 = make_float2(acc[mt][nt][2] + bv1, acc[mt][nt][3] + bv1);
            *(float2*)&out[((size_t)b * Tq + r0) * Eq + ec + nt * 8] = v0;
            *(float2*)&out[((size_t)b * Tq + r1) * Eq + ec + nt * 8] = v1;
        }
    }
}

extern "C" void kernel_launch(void* const* d_in, const int* in_sizes, int n_in,
                              void* d_out, int out_size) {
    const float* x      = (const float*)d_in[0];
    const float* weight = (const float*)d_in[1];
    const float* bias   = (const float*)d_in[2];
    float* out          = (float*)d_out;

    static bool attr_set = false;
    if (!attr_set) {
        cudaFuncSetAttribute(toeplitz_mma_kernel,
                             cudaFuncAttributeMaxDynamicSharedMemorySize,
                             SMEM_BYTES);
        attr_set = true;
    }
    dim3 grid(Eq / TE, Tq / TS, Bq);   // (32, 16, 8) = 4096 blocks
    toeplitz_mma_kernel<<<grid, 128, SMEM_BYTES>>>(x, weight, bias, out);
}